// round 1
// baseline (speedup 1.0000x reference)
#include <cuda_runtime.h>

// y = x @ (W * M)^T with M = identity  ==>  y[b, j] = x[b, j] * W[j, j] * M[j, j]
// Pure HBM-streaming problem: 128 MiB in + 128 MiB out.

#define D 2048
#define B 16384

// Scratch for the effective diagonal (allocation-free per harness rules).
__device__ float g_diag[D];

__global__ void extract_diag_kernel(const float* __restrict__ weight,
                                    const float* __restrict__ mask) {
    int d = blockIdx.x * blockDim.x + threadIdx.x;
    if (d < D) {
        // element (d, d) of a row-major DxD matrix
        size_t idx = (size_t)d * (D + 1);
        g_diag[d] = weight[idx] * mask[idx];
    }
}

__global__ void diag_scale_kernel(const float4* __restrict__ x,
                                  float4* __restrict__ out,
                                  int n4) {
    int i = blockIdx.x * blockDim.x + threadIdx.x;
    if (i >= n4) return;
    // D/4 = 512 float4 per row; column (in float4 units) = i % 512
    int c4 = (i & (D / 4 - 1)) << 2;  // starting scalar column

    float4 v = x[i];
    float s0 = g_diag[c4 + 0];
    float s1 = g_diag[c4 + 1];
    float s2 = g_diag[c4 + 2];
    float s3 = g_diag[c4 + 3];

    v.x *= s0;
    v.y *= s1;
    v.z *= s2;
    v.w *= s3;
    out[i] = v;
}

extern "C" void kernel_launch(void* const* d_in, const int* in_sizes, int n_in,
                              void* d_out, int out_size) {
    const float* x      = (const float*)d_in[0];
    const float* weight = (const float*)d_in[1];
    const float* mask   = (const float*)d_in[2];
    float*       out    = (float*)d_out;

    extract_diag_kernel<<<(D + 255) / 256, 256>>>(weight, mask);

    const int n4 = (B * D) / 4;  // 8,388,608 float4 elements
    const int threads = 256;
    const int blocks = (n4 + threads - 1) / threads;
    diag_scale_kernel<<<blocks, threads>>>((const float4*)x, (float4*)out, n4);
}

// round 2
// speedup vs baseline: 1.0565x; 1.0565x over previous
#include <cuda_runtime.h>

// y = x @ (W * M)^T with M = identity  ==>  y[b, j] = x[b, j] * W[j, j] * M[j, j]
// Pure HBM-streaming problem: 128 MiB in + 128 MiB out.

#define D 2048
#define B 16384
#define C4 (D / 4)          // 512 float4 per row
#define ROWS_PER_THREAD 4

// Scratch for the effective diagonal (allocation-free per harness rules).
__device__ float g_diag[D];

__global__ void extract_diag_kernel(const float* __restrict__ weight,
                                    const float* __restrict__ mask) {
    int d = blockIdx.x * blockDim.x + threadIdx.x;
    if (d < D) {
        size_t idx = (size_t)d * (D + 1);   // element (d, d) row-major
        g_diag[d] = weight[idx] * mask[idx];
    }
}

__global__ __launch_bounds__(256)
void diag_scale_kernel(const float4* __restrict__ x,
                       float4* __restrict__ out) {
    // Thread t handles rows [r, r+3] at column-chunk c4 (4 scalar cols).
    int t = blockIdx.x * blockDim.x + threadIdx.x;
    int c4  = t & (C4 - 1);
    int row = (t >> 9) * ROWS_PER_THREAD;   // t / 512 * 4

    // One vectorized diag load, reused across 4 rows (L1/L2 resident, 8KB).
    float4 s = __ldg((const float4*)&g_diag[c4 << 2]);

    const float4* xp = x + (size_t)row * C4 + c4;
    float4*       op = out + (size_t)row * C4 + c4;

    // 4 independent streaming loads in flight (MLP=4), evict-first.
    float4 v0 = __ldcs(xp + 0 * C4);
    float4 v1 = __ldcs(xp + 1 * C4);
    float4 v2 = __ldcs(xp + 2 * C4);
    float4 v3 = __ldcs(xp + 3 * C4);

    v0.x *= s.x; v0.y *= s.y; v0.z *= s.z; v0.w *= s.w;
    v1.x *= s.x; v1.y *= s.y; v1.z *= s.z; v1.w *= s.w;
    v2.x *= s.x; v2.y *= s.y; v2.z *= s.z; v2.w *= s.w;
    v3.x *= s.x; v3.y *= s.y; v3.z *= s.z; v3.w *= s.w;

    __stcs(op + 0 * C4, v0);
    __stcs(op + 1 * C4, v1);
    __stcs(op + 2 * C4, v2);
    __stcs(op + 3 * C4, v3);
}

extern "C" void kernel_launch(void* const* d_in, const int* in_sizes, int n_in,
                              void* d_out, int out_size) {
    const float* x      = (const float*)d_in[0];
    const float* weight = (const float*)d_in[1];
    const float* mask   = (const float*)d_in[2];
    float*       out    = (float*)d_out;

    extract_diag_kernel<<<(D + 255) / 256, 256>>>(weight, mask);

    // (B / ROWS_PER_THREAD) * C4 threads = 2,097,152 -> 8192 blocks of 256
    const int total_threads = (B / ROWS_PER_THREAD) * C4;
    diag_scale_kernel<<<total_threads / 256, 256>>>((const float4*)x, (float4*)out);
}